// round 8
// baseline (speedup 1.0000x reference)
#include <cuda_runtime.h>
#include <cuda_bf16.h>

#define CROP   7
#define NCELL  49
#define CCH    256     // channels
#define BASE_H 256     // level-2 feature H (=W)

__global__ __launch_bounds__(256, 5)
void roi_align_kernel(const float* __restrict__ f2,
                      const float* __restrict__ f3,
                      const float* __restrict__ f4,
                      const float* __restrict__ f5,
                      const float* __restrict__ boxes,
                      float* __restrict__ out,
                      int N)
{
    const int bid  = blockIdx.x;
    const int bn   = bid >> 2;            // box id in [0, B*N)
    const int quad = bid & 3;             // quarter-box work unit
    const int b    = bn / N;
    const int tid  = threadIdx.x;

    // ---- per-row / per-col sampling tables (+ precombined offsets) ----
    __shared__ float s_ky[CROP][2];
    __shared__ float s_kx[CROP][2];
    __shared__ int   s_yoff[CROP][2];   // yi * Wl * CCH
    __shared__ int   s_xoff[CROP][2];   // xi * CCH
    __shared__ const float* s_fb;       // level base pointer for this image

    if (tid < 2 * CROP) {
        const float* bx = boxes + (size_t)bn * 4;
        float by0 = bx[0], bx0 = bx[1], by1 = bx[2], bx1 = bx[3];
        float bh = by1 - by0;
        float bw = bx1 - bx0;

        // level assignment: floor(log2(sqrt(h*w)/224)) + 4, clipped to [2,5]
        float lev_f = floorf(log2f(sqrtf(bh * bw) / 224.0f)) + 4.0f;
        lev_f = fminf(fmaxf(lev_f, 2.0f), 5.0f);
        int   lev  = (int)lev_f;
        int   lev0 = lev - 2;

        float inv_scale = exp2f(-(float)lev);   // exact (power of two)
        float y0b = by0 * inv_scale;
        float x0b = bx0 * inv_scale;
        bh *= inv_scale;
        bw *= inv_scale;

        int   Wl  = BASE_H >> lev0;             // H_l == W_l (square levels)
        float bnd = (float)Wl - 1.0f;

        int  i   = (tid < CROP) ? tid : (tid - CROP);
        bool isx = (tid >= CROP);
        // match JAX op order: (i + 0.5) * extent / CROP   (mul then div)
        float g  = (isx ? x0b : y0b) + ((float)i + 0.5f) * (isx ? bw : bh) / 7.0f;
        float c0 = fminf(fmaxf(floorf(g), 0.0f), bnd);
        float c1 = fminf(c0 + 1.0f, bnd);
        float l  = g - c0;                       // may be <0 or >1 (clipped), as in ref
        if (isx) {
            s_kx[i][0]   = 1.0f - l; s_kx[i][1] = l;
            s_xoff[i][0] = (int)c0 * CCH;
            s_xoff[i][1] = (int)c1 * CCH;
        } else {
            s_ky[i][0]   = 1.0f - l; s_ky[i][1] = l;
            s_yoff[i][0] = (int)c0 * Wl * CCH;
            s_yoff[i][1] = (int)c1 * Wl * CCH;
        }
        if (tid == 0) {
            const float* fp = (lev0 == 0) ? f2 : (lev0 == 1) ? f3
                            : (lev0 == 2) ? f4 : f5;
            s_fb = fp + (size_t)b * Wl * Wl * CCH;
        }
    }
    __syncthreads();

    const float* fb = s_fb;

    // ---- cell range for this quarter: 12,12,12,13 cells ----
    const int cstart = quad * 12;
    const int cend   = (quad == 3) ? NCELL : (cstart + 12);

    // 8 cell-groups x 32 lanes; each lane does 2 float4 per corner row (MLP=8)
    const int group = tid >> 5;     // 0..7
    const int lane  = tid & 31;     // float4 index; covers lane and lane+32

    float* obase = out + (size_t)bn * NCELL * CCH;

    for (int cell = cstart + group; cell < cend; cell += 8) {
        int p = cell / CROP;
        int q = cell - p * CROP;

        int ra = s_yoff[p][0], rb = s_yoff[p][1];
        int ca = s_xoff[q][0], cb = s_xoff[q][1];

        const float4* r00 = (const float4*)(fb + ra + ca) + lane;
        const float4* r01 = (const float4*)(fb + ra + cb) + lane;
        const float4* r10 = (const float4*)(fb + rb + ca) + lane;
        const float4* r11 = (const float4*)(fb + rb + cb) + lane;

        // 8 independent loads, front-batched; +32 is an immediate offset
        float4 a00 = r00[0];  float4 b00 = r00[32];
        float4 a01 = r01[0];  float4 b01 = r01[32];
        float4 a10 = r10[0];  float4 b10 = r10[32];
        float4 a11 = r11[0];  float4 b11 = r11[32];

        float ky0 = s_ky[p][0], ky1 = s_ky[p][1];
        float kx0 = s_kx[q][0], kx1 = s_kx[q][1];
        float w00 = ky0 * kx0, w01 = ky0 * kx1;
        float w10 = ky1 * kx0, w11 = ky1 * kx1;

        float4 oa, ob;
        oa.x = w00 * a00.x + w01 * a01.x + w10 * a10.x + w11 * a11.x;
        oa.y = w00 * a00.y + w01 * a01.y + w10 * a10.y + w11 * a11.y;
        oa.z = w00 * a00.z + w01 * a01.z + w10 * a10.z + w11 * a11.z;
        oa.w = w00 * a00.w + w01 * a01.w + w10 * a10.w + w11 * a11.w;
        ob.x = w00 * b00.x + w01 * b01.x + w10 * b10.x + w11 * b11.x;
        ob.y = w00 * b00.y + w01 * b01.y + w10 * b10.y + w11 * b11.y;
        ob.z = w00 * b00.z + w01 * b01.z + w10 * b10.z + w11 * b11.z;
        ob.w = w00 * b00.w + w01 * b01.w + w10 * b10.w + w11 * b11.w;

        float4* op = (float4*)(obase + (size_t)cell * CCH) + lane;
        op[0]  = oa;
        op[32] = ob;
    }
}

extern "C" void kernel_launch(void* const* d_in, const int* in_sizes, int n_in,
                              void* d_out, int out_size)
{
    const float* f2    = (const float*)d_in[0];
    const float* f3    = (const float*)d_in[1];
    const float* f4    = (const float*)d_in[2];
    const float* f5    = (const float*)d_in[3];
    const float* boxes = (const float*)d_in[4];
    float* out = (float*)d_out;

    int BN = in_sizes[4] / 4;                       // B * N boxes
    int B  = in_sizes[0] / (256 * 256 * 256);       // feat2 is [B,256,256,256]
    int N  = BN / B;

    roi_align_kernel<<<BN * 4, 256>>>(f2, f3, f4, f5, boxes, out, N);
}

// round 9
// speedup vs baseline: 1.0622x; 1.0622x over previous
#include <cuda_runtime.h>
#include <cuda_bf16.h>

#define CROP   7
#define NCELL  49
#define CCH    256     // channels
#define BASE_H 256     // level-2 feature H (=W)

__global__ __launch_bounds__(256, 5)
void roi_align_kernel(const float* __restrict__ f2,
                      const float* __restrict__ f3,
                      const float* __restrict__ f4,
                      const float* __restrict__ f5,
                      const float* __restrict__ boxes,
                      float* __restrict__ out,
                      int N)
{
    const int bn  = blockIdx.x;           // box id in [0, B*N)
    const int b   = bn / N;
    const int tid = threadIdx.x;

    // ---- per-row / per-col sampling tables (+ precombined offsets) ----
    __shared__ float s_ky[CROP][2];
    __shared__ float s_kx[CROP][2];
    __shared__ int   s_yoff[CROP][2];   // yi * Wl * CCH
    __shared__ int   s_xoff[CROP][2];   // xi * CCH
    __shared__ const float* s_fb;       // level base pointer for this image

    if (tid < 2 * CROP) {
        const float* bx = boxes + (size_t)bn * 4;
        float by0 = bx[0], bx0 = bx[1], by1 = bx[2], bx1 = bx[3];
        float bh = by1 - by0;
        float bw = bx1 - bx0;

        // level assignment: floor(log2(sqrt(h*w)/224)) + 4, clipped to [2,5]
        float lev_f = floorf(log2f(sqrtf(bh * bw) / 224.0f)) + 4.0f;
        lev_f = fminf(fmaxf(lev_f, 2.0f), 5.0f);
        int   lev  = (int)lev_f;
        int   lev0 = lev - 2;

        float inv_scale = exp2f(-(float)lev);   // exact (power of two)
        float y0b = by0 * inv_scale;
        float x0b = bx0 * inv_scale;
        bh *= inv_scale;
        bw *= inv_scale;

        int   Wl  = BASE_H >> lev0;             // H_l == W_l (square levels)
        float bnd = (float)Wl - 1.0f;

        int  i   = (tid < CROP) ? tid : (tid - CROP);
        bool isx = (tid >= CROP);
        // match JAX op order: (i + 0.5) * extent / CROP   (mul then div)
        float g  = (isx ? x0b : y0b) + ((float)i + 0.5f) * (isx ? bw : bh) / 7.0f;
        float c0 = fminf(fmaxf(floorf(g), 0.0f), bnd);
        float c1 = fminf(c0 + 1.0f, bnd);
        float l  = g - c0;                       // may be <0 or >1 (clipped), as in ref
        if (isx) {
            s_kx[i][0]   = 1.0f - l; s_kx[i][1] = l;
            s_xoff[i][0] = (int)c0 * CCH;
            s_xoff[i][1] = (int)c1 * CCH;
        } else {
            s_ky[i][0]   = 1.0f - l; s_ky[i][1] = l;
            s_yoff[i][0] = (int)c0 * Wl * CCH;
            s_yoff[i][1] = (int)c1 * Wl * CCH;
        }
        if (tid == 0) {
            const float* fp = (lev0 == 0) ? f2 : (lev0 == 1) ? f3
                            : (lev0 == 2) ? f4 : f5;
            s_fb = fp + (size_t)b * Wl * Wl * CCH;
        }
    }
    __syncthreads();

    const float* fb = s_fb;

    // ---- main loop: 4 cell-groups x 64 lanes; float2 accesses ----
    // Each warp's LDG.64 touches 2 x 128B lines (vs 4 for LDG.128) -> fewer
    // within-instruction L1tex wavefront replays at the same bytes and MLP=8.
    const int group = tid >> 6;     // 0..3
    const int lane  = tid & 63;     // float2 index; covers lane and lane+64

    float* obase = out + (size_t)bn * NCELL * CCH;

    for (int cell = group; cell < NCELL; cell += 4) {
        int p = cell / CROP;
        int q = cell - p * CROP;

        int ra = s_yoff[p][0], rb = s_yoff[p][1];
        int ca = s_xoff[q][0], cb = s_xoff[q][1];

        const float2* r00 = (const float2*)(fb + ra + ca) + lane;
        const float2* r01 = (const float2*)(fb + ra + cb) + lane;
        const float2* r10 = (const float2*)(fb + rb + ca) + lane;
        const float2* r11 = (const float2*)(fb + rb + cb) + lane;

        // 8 independent LDG.64, front-batched; +64 is an immediate offset
        float2 a00 = r00[0];  float2 b00 = r00[64];
        float2 a01 = r01[0];  float2 b01 = r01[64];
        float2 a10 = r10[0];  float2 b10 = r10[64];
        float2 a11 = r11[0];  float2 b11 = r11[64];

        float ky0 = s_ky[p][0], ky1 = s_ky[p][1];
        float kx0 = s_kx[q][0], kx1 = s_kx[q][1];
        float w00 = ky0 * kx0, w01 = ky0 * kx1;
        float w10 = ky1 * kx0, w11 = ky1 * kx1;

        float2 oa, ob;
        oa.x = w00 * a00.x + w01 * a01.x + w10 * a10.x + w11 * a11.x;
        oa.y = w00 * a00.y + w01 * a01.y + w10 * a10.y + w11 * a11.y;
        ob.x = w00 * b00.x + w01 * b01.x + w10 * b10.x + w11 * b11.x;
        ob.y = w00 * b00.y + w01 * b01.y + w10 * b10.y + w11 * b11.y;

        float2* op = (float2*)(obase + (size_t)cell * CCH) + lane;
        op[0]  = oa;
        op[64] = ob;
    }
}

extern "C" void kernel_launch(void* const* d_in, const int* in_sizes, int n_in,
                              void* d_out, int out_size)
{
    const float* f2    = (const float*)d_in[0];
    const float* f3    = (const float*)d_in[1];
    const float* f4    = (const float*)d_in[2];
    const float* f5    = (const float*)d_in[3];
    const float* boxes = (const float*)d_in[4];
    float* out = (float*)d_out;

    int BN = in_sizes[4] / 4;                       // B * N boxes
    int B  = in_sizes[0] / (256 * 256 * 256);       // feat2 is [B,256,256,256]
    int N  = BN / B;

    roi_align_kernel<<<BN, 256>>>(f2, f3, f4, f5, boxes, out, N);
}

// round 10
// speedup vs baseline: 1.1360x; 1.0695x over previous
#include <cuda_runtime.h>
#include <cuda_bf16.h>

#define CROP   7
#define NCELL  49
#define CCH    256     // channels
#define BASE_H 256     // level-2 feature H (=W)

// 224 threads = 7 groups x 32 lanes: 49 cells / 7 groups = exactly 7 iterations
// per warp (perfect balance), and 6 CTAs/SM x 7 warps = 42 warps at 48 regs.
__global__ __launch_bounds__(224, 6)
void roi_align_kernel(const float* __restrict__ f2,
                      const float* __restrict__ f3,
                      const float* __restrict__ f4,
                      const float* __restrict__ f5,
                      const float* __restrict__ boxes,
                      float* __restrict__ out,
                      int N)
{
    const int bn  = blockIdx.x;           // box id in [0, B*N)
    const int b   = bn / N;
    const int tid = threadIdx.x;

    // ---- per-row / per-col sampling tables (+ precombined offsets) ----
    __shared__ float s_ky[CROP][2];
    __shared__ float s_kx[CROP][2];
    __shared__ int   s_yoff[CROP][2];   // yi * Wl * CCH
    __shared__ int   s_xoff[CROP][2];   // xi * CCH
    __shared__ const float* s_fb;       // level base pointer for this image

    if (tid < 2 * CROP) {
        const float* bx = boxes + (size_t)bn * 4;
        float by0 = bx[0], bx0 = bx[1], by1 = bx[2], bx1 = bx[3];
        float bh = by1 - by0;
        float bw = bx1 - bx0;

        // level assignment: floor(log2(sqrt(h*w)/224)) + 4, clipped to [2,5]
        float lev_f = floorf(log2f(sqrtf(bh * bw) / 224.0f)) + 4.0f;
        lev_f = fminf(fmaxf(lev_f, 2.0f), 5.0f);
        int   lev  = (int)lev_f;
        int   lev0 = lev - 2;

        float inv_scale = exp2f(-(float)lev);   // exact (power of two)
        float y0b = by0 * inv_scale;
        float x0b = bx0 * inv_scale;
        bh *= inv_scale;
        bw *= inv_scale;

        int   Wl  = BASE_H >> lev0;             // H_l == W_l (square levels)
        float bnd = (float)Wl - 1.0f;

        int  i   = (tid < CROP) ? tid : (tid - CROP);
        bool isx = (tid >= CROP);
        // match JAX op order: (i + 0.5) * extent / CROP   (mul then div)
        float g  = (isx ? x0b : y0b) + ((float)i + 0.5f) * (isx ? bw : bh) / 7.0f;
        float c0 = fminf(fmaxf(floorf(g), 0.0f), bnd);
        float c1 = fminf(c0 + 1.0f, bnd);
        float l  = g - c0;                       // may be <0 or >1 (clipped), as in ref
        if (isx) {
            s_kx[i][0]   = 1.0f - l; s_kx[i][1] = l;
            s_xoff[i][0] = (int)c0 * CCH;
            s_xoff[i][1] = (int)c1 * CCH;
        } else {
            s_ky[i][0]   = 1.0f - l; s_ky[i][1] = l;
            s_yoff[i][0] = (int)c0 * Wl * CCH;
            s_yoff[i][1] = (int)c1 * Wl * CCH;
        }
        if (tid == 0) {
            const float* fp = (lev0 == 0) ? f2 : (lev0 == 1) ? f3
                            : (lev0 == 2) ? f4 : f5;
            s_fb = fp + (size_t)b * Wl * Wl * CCH;
        }
    }
    __syncthreads();

    const float* fb = s_fb;

    // ---- main loop: 7 cell-groups x 32 lanes; 2 float4 per corner row ----
    // Each thread issues 8 independent LDG.128 per iteration (MLP=8).
    const int group = tid >> 5;     // 0..6
    const int lane  = tid & 31;     // float4 index; covers lane and lane+32

    float* obase = out + (size_t)bn * NCELL * CCH;

    #pragma unroll 1
    for (int cell = group; cell < NCELL; cell += 7) {
        int p = cell / CROP;
        int q = cell - p * CROP;

        int ra = s_yoff[p][0], rb = s_yoff[p][1];
        int ca = s_xoff[q][0], cb = s_xoff[q][1];

        const float4* r00 = (const float4*)(fb + ra + ca) + lane;
        const float4* r01 = (const float4*)(fb + ra + cb) + lane;
        const float4* r10 = (const float4*)(fb + rb + ca) + lane;
        const float4* r11 = (const float4*)(fb + rb + cb) + lane;

        // 8 independent loads, front-batched; +32 is an immediate offset
        float4 a00 = r00[0];  float4 b00 = r00[32];
        float4 a01 = r01[0];  float4 b01 = r01[32];
        float4 a10 = r10[0];  float4 b10 = r10[32];
        float4 a11 = r11[0];  float4 b11 = r11[32];

        float ky0 = s_ky[p][0], ky1 = s_ky[p][1];
        float kx0 = s_kx[q][0], kx1 = s_kx[q][1];
        float w00 = ky0 * kx0, w01 = ky0 * kx1;
        float w10 = ky1 * kx0, w11 = ky1 * kx1;

        float4 oa, ob;
        oa.x = w00 * a00.x + w01 * a01.x + w10 * a10.x + w11 * a11.x;
        oa.y = w00 * a00.y + w01 * a01.y + w10 * a10.y + w11 * a11.y;
        oa.z = w00 * a00.z + w01 * a01.z + w10 * a10.z + w11 * a11.z;
        oa.w = w00 * a00.w + w01 * a01.w + w10 * a10.w + w11 * a11.w;
        ob.x = w00 * b00.x + w01 * b01.x + w10 * b10.x + w11 * b11.x;
        ob.y = w00 * b00.y + w01 * b01.y + w10 * b10.y + w11 * b11.y;
        ob.z = w00 * b00.z + w01 * b01.z + w10 * b10.z + w11 * b11.z;
        ob.w = w00 * b00.w + w01 * b01.w + w10 * b10.w + w11 * b11.w;

        float4* op = (float4*)(obase + (size_t)cell * CCH) + lane;
        op[0]  = oa;
        op[32] = ob;
    }
}

extern "C" void kernel_launch(void* const* d_in, const int* in_sizes, int n_in,
                              void* d_out, int out_size)
{
    const float* f2    = (const float*)d_in[0];
    const float* f3    = (const float*)d_in[1];
    const float* f4    = (const float*)d_in[2];
    const float* f5    = (const float*)d_in[3];
    const float* boxes = (const float*)d_in[4];
    float* out = (float*)d_out;

    int BN = in_sizes[4] / 4;                       // B * N boxes
    int B  = in_sizes[0] / (256 * 256 * 256);       // feat2 is [B,256,256,256]
    int N  = BN / B;

    roi_align_kernel<<<BN, 224>>>(f2, f3, f4, f5, boxes, out, N);
}

// round 11
// speedup vs baseline: 1.2338x; 1.0860x over previous
#include <cuda_runtime.h>
#include <cuda_bf16.h>

#define CROP   7
#define NCELL  49
#define CCH    256     // channels
#define BASE_H 256     // level-2 feature H (=W)

__global__ __launch_bounds__(256, 5)
void roi_align_kernel(const float* __restrict__ f2,
                      const float* __restrict__ f3,
                      const float* __restrict__ f4,
                      const float* __restrict__ f5,
                      const float* __restrict__ boxes,
                      float* __restrict__ out,
                      int N)
{
    const int bn  = blockIdx.x;           // box id in [0, B*N)
    const int b   = bn / N;
    const int tid = threadIdx.x;

    // ---- per-row / per-col sampling tables (+ precombined offsets) ----
    __shared__ float s_ky[CROP][2];
    __shared__ float s_kx[CROP][2];
    __shared__ int   s_yoff[CROP][2];   // yi * Wl * CCH
    __shared__ int   s_xoff[CROP][2];   // xi * CCH
    __shared__ const float* s_fb;       // level base pointer for this image

    if (tid < 2 * CROP) {
        const float* bx = boxes + (size_t)bn * 4;
        float by0 = bx[0], bx0 = bx[1], by1 = bx[2], bx1 = bx[3];
        float bh = by1 - by0;
        float bw = bx1 - bx0;

        // level assignment: floor(log2(sqrt(h*w)/224)) + 4, clipped to [2,5]
        float lev_f = floorf(log2f(sqrtf(bh * bw) / 224.0f)) + 4.0f;
        lev_f = fminf(fmaxf(lev_f, 2.0f), 5.0f);
        int   lev  = (int)lev_f;
        int   lev0 = lev - 2;

        float inv_scale = exp2f(-(float)lev);   // exact (power of two)
        float y0b = by0 * inv_scale;
        float x0b = bx0 * inv_scale;
        bh *= inv_scale;
        bw *= inv_scale;

        int   Wl  = BASE_H >> lev0;             // H_l == W_l (square levels)
        float bnd = (float)Wl - 1.0f;

        int  i   = (tid < CROP) ? tid : (tid - CROP);
        bool isx = (tid >= CROP);
        // match JAX op order: (i + 0.5) * extent / CROP   (mul then div)
        float g  = (isx ? x0b : y0b) + ((float)i + 0.5f) * (isx ? bw : bh) / 7.0f;
        float c0 = fminf(fmaxf(floorf(g), 0.0f), bnd);
        float c1 = fminf(c0 + 1.0f, bnd);
        float l  = g - c0;                       // may be <0 or >1 (clipped), as in ref
        if (isx) {
            s_kx[i][0]   = 1.0f - l; s_kx[i][1] = l;
            s_xoff[i][0] = (int)c0 * CCH;
            s_xoff[i][1] = (int)c1 * CCH;
        } else {
            s_ky[i][0]   = 1.0f - l; s_ky[i][1] = l;
            s_yoff[i][0] = (int)c0 * Wl * CCH;
            s_yoff[i][1] = (int)c1 * Wl * CCH;
        }
        if (tid == 0) {
            const float* fp = (lev0 == 0) ? f2 : (lev0 == 1) ? f3
                            : (lev0 == 2) ? f4 : f5;
            s_fb = fp + (size_t)b * Wl * Wl * CCH;
        }
    }
    __syncthreads();

    const float* fb = s_fb;

    // ---- main loop: 8 cell-groups x 32 lanes; 2 float4 per corner row ----
    // Each thread issues 8 independent LDG.128 per iteration (MLP=8),
    // via the non-coherent read-only path (features are never written).
    const int group = tid >> 5;     // 0..7
    const int lane  = tid & 31;     // float4 index; covers lane and lane+32

    float* obase = out + (size_t)bn * NCELL * CCH;

    for (int cell = group; cell < NCELL; cell += 8) {
        int p = cell / CROP;
        int q = cell - p * CROP;

        int ra = s_yoff[p][0], rb = s_yoff[p][1];
        int ca = s_xoff[q][0], cb = s_xoff[q][1];

        const float4* r00 = (const float4*)(fb + ra + ca) + lane;
        const float4* r01 = (const float4*)(fb + ra + cb) + lane;
        const float4* r10 = (const float4*)(fb + rb + ca) + lane;
        const float4* r11 = (const float4*)(fb + rb + cb) + lane;

        // 8 independent loads, front-batched; +32 is an immediate offset
        float4 a00 = __ldg(r00);  float4 b00 = __ldg(r00 + 32);
        float4 a01 = __ldg(r01);  float4 b01 = __ldg(r01 + 32);
        float4 a10 = __ldg(r10);  float4 b10 = __ldg(r10 + 32);
        float4 a11 = __ldg(r11);  float4 b11 = __ldg(r11 + 32);

        float ky0 = s_ky[p][0], ky1 = s_ky[p][1];
        float kx0 = s_kx[q][0], kx1 = s_kx[q][1];
        float w00 = ky0 * kx0, w01 = ky0 * kx1;
        float w10 = ky1 * kx0, w11 = ky1 * kx1;

        float4 oa, ob;
        oa.x = w00 * a00.x + w01 * a01.x + w10 * a10.x + w11 * a11.x;
        oa.y = w00 * a00.y + w01 * a01.y + w10 * a10.y + w11 * a11.y;
        oa.z = w00 * a00.z + w01 * a01.z + w10 * a10.z + w11 * a11.z;
        oa.w = w00 * a00.w + w01 * a01.w + w10 * a10.w + w11 * a11.w;
        ob.x = w00 * b00.x + w01 * b01.x + w10 * b10.x + w11 * b11.x;
        ob.y = w00 * b00.y + w01 * b01.y + w10 * b10.y + w11 * b11.y;
        ob.z = w00 * b00.z + w01 * b01.z + w10 * b10.z + w11 * b11.z;
        ob.w = w00 * b00.w + w01 * b01.w + w10 * b10.w + w11 * b11.w;

        float4* op = (float4*)(obase + (size_t)cell * CCH) + lane;
        op[0]  = oa;
        op[32] = ob;
    }
}

extern "C" void kernel_launch(void* const* d_in, const int* in_sizes, int n_in,
                              void* d_out, int out_size)
{
    const float* f2    = (const float*)d_in[0];
    const float* f3    = (const float*)d_in[1];
    const float* f4    = (const float*)d_in[2];
    const float* f5    = (const float*)d_in[3];
    const float* boxes = (const float*)d_in[4];
    float* out = (float*)d_out;

    int BN = in_sizes[4] / 4;                       // B * N boxes
    int B  = in_sizes[0] / (256 * 256 * 256);       // feat2 is [B,256,256,256]
    int N  = BN / B;

    roi_align_kernel<<<BN, 256>>>(f2, f3, f4, f5, boxes, out, N);
}